// round 1
// baseline (speedup 1.0000x reference)
#include <cuda_runtime.h>
#include <cuda_bf16.h>
#include <cstddef>

// Problem constants (fixed shapes per reference)
constexpr int B_ = 16;
constexpr int C_ = 256;
constexpr int L_ = 8192;
constexpr int D_ = 512;   // d_inner
constexpr int A_ = 64;    // att_dim

// Scratch: u[d] = sum_a w_out[d,a]*wv[a]; coef = <wq,wk>/sqrt(att_dim)
__device__ float g_u[D_];
__device__ float g_coef;

__global__ void prep_kernel(const float* __restrict__ wq,
                            const float* __restrict__ wk,
                            const float* __restrict__ wv,
                            const float* __restrict__ w_out) {
    int d = threadIdx.x;  // 512 threads
    float acc = 0.f;
    const float* row = w_out + d * A_;
#pragma unroll
    for (int a = 0; a < A_; a++) acc += row[a] * wv[a];
    g_u[d] = acc;
    if (d == 0) {
        float qk = 0.f;
#pragma unroll
        for (int a = 0; a < A_; a++) qk += wq[a] * wk[a];
        g_coef = qk * 0.125f;  // 1/sqrt(64)
    }
}

// One block = (one b, 32 consecutive l). 256 threads = 8 c-groups x 32 l.
// Each thread keeps its 32 h values in registers -> h_v read exactly once.
__global__ void __launch_bounds__(256)
pool_outer_kernel(const float* __restrict__ h_v, float* __restrict__ out) {
    __shared__ float s_u[D_];
    __shared__ float s_red[256];
    __shared__ float s_red2[256];
    __shared__ float s_sval[32];
    __shared__ __align__(16) float s_pooled[32];

    const int tid = threadIdx.x;
    const int ll  = tid & 31;   // l within tile
    const int cg  = tid >> 5;   // c-group 0..7

    const int bidx   = blockIdx.x;          // 16 * 256 = 4096 blocks
    const int b      = bidx >> 8;           // L/32 = 256 tiles per batch
    const int l_base = (bidx & 255) << 5;

    // stage u into smem (2 per thread)
    s_u[tid]       = g_u[tid];
    s_u[tid + 256] = g_u[tid + 256];

    // ---- single read of h_v: 32 values per thread, coalesced per warp ----
    const float* p = h_v + ((size_t)b * C_ + (size_t)cg * 32) * L_ + l_base + ll;
    float h[32];
#pragma unroll
    for (int i = 0; i < 32; i++) h[i] = p[(size_t)i * L_];

    // ---- mean over C ----
    float sum = 0.f;
#pragma unroll
    for (int i = 0; i < 32; i++) sum += h[i];
    s_red[tid] = sum;
    __syncthreads();
    if (tid < 32) {
        float t = 0.f;
#pragma unroll
        for (int j = 0; j < 8; j++) t += s_red[tid + 32 * j];
        s_sval[tid] = t * (1.0f / 256.0f);
    }
    __syncthreads();

    const float coef2 = s_sval[ll] * g_coef;  // per-l logit scale

    // ---- softmax-weighted sum (max-free: |logit| <~ 1.2) ----
    float se = 0.f, seh = 0.f;
#pragma unroll
    for (int i = 0; i < 32; i++) {
        float e = __expf(h[i] * coef2);
        se  += e;
        seh += e * h[i];
    }
    s_red[tid]  = se;
    s_red2[tid] = seh;
    __syncthreads();
    if (tid < 32) {
        float te = 0.f, teh = 0.f;
#pragma unroll
        for (int j = 0; j < 8; j++) {
            te  += s_red[tid + 32 * j];
            teh += s_red2[tid + 32 * j];
        }
        s_pooled[tid] = teh / te;
    }
    __syncthreads();

    // ---- epilogue: out[b,d,l] = pooled[b,l] * u[d], float4 streaming stores ----
    const float4* pool4 = reinterpret_cast<const float4*>(s_pooled);  // 8 float4
    float4* out4 = reinterpret_cast<float4*>(out + (size_t)b * D_ * L_ + l_base);
    // 512 d-rows x 8 float4 = 4096 vec stores per block; 16 per thread
#pragma unroll
    for (int k = 0; k < 16; k++) {
        int idx = k * 256 + tid;
        int d   = idx >> 3;
        int lq  = idx & 7;
        float ud = s_u[d];
        float4 pv = pool4[lq];
        float4 v  = make_float4(pv.x * ud, pv.y * ud, pv.z * ud, pv.w * ud);
        out4[(size_t)d * (L_ / 4) + lq] = v;
    }
}

extern "C" void kernel_launch(void* const* d_in, const int* in_sizes, int n_in,
                              void* d_out, int out_size) {
    const float* h_v   = (const float*)d_in[0];  // [B, C, L]
    const float* wq    = (const float*)d_in[1];  // [64]
    const float* wk    = (const float*)d_in[2];  // [64]
    const float* wv    = (const float*)d_in[3];  // [64]
    const float* w_out = (const float*)d_in[4];  // [512, 64]
    float* out = (float*)d_out;                  // [B, 512, L]

    prep_kernel<<<1, D_>>>(wq, wk, wv, w_out);
    pool_outer_kernel<<<B_ * (L_ / 32), 256>>>(h_v, out);
}

// round 2
// speedup vs baseline: 1.0512x; 1.0512x over previous
#include <cuda_runtime.h>
#include <cuda_bf16.h>
#include <cstddef>

// Problem constants (fixed shapes per reference)
constexpr int B_ = 16;
constexpr int C_ = 256;
constexpr int L_ = 8192;
constexpr int D_ = 512;   // d_inner
constexpr int A_ = 64;    // att_dim

// Scratch: u[d] = sum_a w_out[d,a]*wv[a]; coef = <wq,wk>/sqrt(att_dim)
__device__ float g_u[D_];
__device__ float g_coef;

// 32 blocks x 256 threads. Block g computes u[d] for d in [g*16, g*16+16).
// Thread layout: dl = t>>4 (16 d's), part = t&15 (16 float4 chunks of the 64-wide row).
__global__ void prep_kernel(const float* __restrict__ wq,
                            const float* __restrict__ wk,
                            const float* __restrict__ wv,
                            const float* __restrict__ w_out) {
    const int t = threadIdx.x;
    const int g = blockIdx.x;
    const int dl   = t >> 4;
    const int part = t & 15;
    const int d = g * 16 + dl;

    const float4* w4  = reinterpret_cast<const float4*>(w_out + (size_t)d * A_);
    const float4  wv4 = reinterpret_cast<const float4*>(wv)[part];
    const float4  a4  = w4[part];
    float acc = a4.x * wv4.x + a4.y * wv4.y + a4.z * wv4.z + a4.w * wv4.w;
#pragma unroll
    for (int m = 1; m < 16; m <<= 1)
        acc += __shfl_xor_sync(0xffffffffu, acc, m);
    if (part == 0) g_u[d] = acc;

    // coef: block 0, warp 0 (t 0..31 is exactly warp 0)
    if (g == 0 && t < 32) {
        float p = wq[t] * wk[t] + wq[t + 32] * wk[t + 32];
#pragma unroll
        for (int m = 16; m >= 1; m >>= 1)
            p += __shfl_xor_sync(0xffffffffu, p, m);
        if (t == 0) g_coef = p * 0.125f;  // 1/sqrt(64)
    }
}

// One block = (one b, 32 consecutive l). 256 threads.
// Thread layout: lq = tid&7 (float4 index -> 4 l's), cg = tid>>3 (8 c's each).
// Each thread keeps 8 float4 (= 8 c x 4 l) in registers -> h_v read exactly once,
// via LDG.128.
__global__ void __launch_bounds__(256)
pool_outer_kernel(const float* __restrict__ h_v, float* __restrict__ out) {
    __shared__ float s_u[D_];
    __shared__ float4 s_part[64];   // [warp][lq]
    __shared__ float4 s_se[64];
    __shared__ float4 s_seh[64];
    __shared__ __align__(16) float s_sval[32];
    __shared__ __align__(16) float s_pooled[32];

    const int tid  = threadIdx.x;
    const int lq   = tid & 7;    // which float4 within the 32-l tile
    const int cg   = tid >> 3;   // c-group 0..31 (8 c each)
    const int warp = tid >> 5;
    const int lane = tid & 31;

    const int bidx   = blockIdx.x;       // 16 * 256 = 4096 blocks
    const int b      = bidx >> 8;
    const int l_base = (bidx & 255) << 5;

    // stage u into smem (2 per thread)
    s_u[tid]       = g_u[tid];
    s_u[tid + 256] = g_u[tid + 256];

    // ---- single read of h_v: 8 x LDG.128 per thread ----
    const float* p = h_v + ((size_t)b * C_ + (size_t)cg * 8) * L_ + l_base + lq * 4;
    float4 h4[8];
#pragma unroll
    for (int i = 0; i < 8; i++)
        h4[i] = __ldcs(reinterpret_cast<const float4*>(p + (size_t)i * L_));

    // ---- mean over C: thread partial (8 c), warp shuffle over 4 cg's, smem over warps ----
    float4 s = make_float4(0.f, 0.f, 0.f, 0.f);
#pragma unroll
    for (int i = 0; i < 8; i++) {
        s.x += h4[i].x; s.y += h4[i].y; s.z += h4[i].z; s.w += h4[i].w;
    }
#pragma unroll
    for (int m = 8; m <= 16; m <<= 1) {
        s.x += __shfl_xor_sync(0xffffffffu, s.x, m);
        s.y += __shfl_xor_sync(0xffffffffu, s.y, m);
        s.z += __shfl_xor_sync(0xffffffffu, s.z, m);
        s.w += __shfl_xor_sync(0xffffffffu, s.w, m);
    }
    if (lane < 8) s_part[warp * 8 + lq] = s;
    __syncthreads();
    if (tid < 8) {
        float4 t = make_float4(0.f, 0.f, 0.f, 0.f);
#pragma unroll
        for (int w = 0; w < 8; w++) {
            float4 v = s_part[w * 8 + tid];
            t.x += v.x; t.y += v.y; t.z += v.z; t.w += v.w;
        }
        const float k = (1.0f / 256.0f) * g_coef;  // fold mean-scale + qk/sqrt(A)
        reinterpret_cast<float4*>(s_sval)[tid] =
            make_float4(t.x * k, t.y * k, t.z * k, t.w * k);
    }
    __syncthreads();

    const float4 cf = reinterpret_cast<const float4*>(s_sval)[lq];

    // ---- softmax-weighted sum (max-free: |logit| bounded ~1.2) ----
    float4 se  = make_float4(0.f, 0.f, 0.f, 0.f);
    float4 seh = make_float4(0.f, 0.f, 0.f, 0.f);
#pragma unroll
    for (int i = 0; i < 8; i++) {
        float4 hv = h4[i];
        float e;
        e = __expf(hv.x * cf.x); se.x += e; seh.x += e * hv.x;
        e = __expf(hv.y * cf.y); se.y += e; seh.y += e * hv.y;
        e = __expf(hv.z * cf.z); se.z += e; seh.z += e * hv.z;
        e = __expf(hv.w * cf.w); se.w += e; seh.w += e * hv.w;
    }
#pragma unroll
    for (int m = 8; m <= 16; m <<= 1) {
        se.x  += __shfl_xor_sync(0xffffffffu, se.x,  m);
        se.y  += __shfl_xor_sync(0xffffffffu, se.y,  m);
        se.z  += __shfl_xor_sync(0xffffffffu, se.z,  m);
        se.w  += __shfl_xor_sync(0xffffffffu, se.w,  m);
        seh.x += __shfl_xor_sync(0xffffffffu, seh.x, m);
        seh.y += __shfl_xor_sync(0xffffffffu, seh.y, m);
        seh.z += __shfl_xor_sync(0xffffffffu, seh.z, m);
        seh.w += __shfl_xor_sync(0xffffffffu, seh.w, m);
    }
    if (lane < 8) { s_se[warp * 8 + lq] = se; s_seh[warp * 8 + lq] = seh; }
    __syncthreads();
    if (tid < 8) {
        float4 te = make_float4(0.f, 0.f, 0.f, 0.f);
        float4 th = make_float4(0.f, 0.f, 0.f, 0.f);
#pragma unroll
        for (int w = 0; w < 8; w++) {
            float4 a = s_se[w * 8 + tid];
            float4 c = s_seh[w * 8 + tid];
            te.x += a.x; te.y += a.y; te.z += a.z; te.w += a.w;
            th.x += c.x; th.y += c.y; th.z += c.z; th.w += c.w;
        }
        reinterpret_cast<float4*>(s_pooled)[tid] =
            make_float4(th.x / te.x, th.y / te.y, th.z / te.z, th.w / te.w);
    }
    __syncthreads();

    // ---- epilogue: out[b,d,l] = pooled[l] * u[d], streaming float4 stores ----
    const float4* pool4 = reinterpret_cast<const float4*>(s_pooled);  // 8 float4
    float4* out4 = reinterpret_cast<float4*>(out + (size_t)b * D_ * L_ + l_base);
#pragma unroll
    for (int k = 0; k < 16; k++) {
        int idx = k * 256 + tid;
        int d   = idx >> 3;
        int q   = idx & 7;
        float ud = s_u[d];
        float4 pv = pool4[q];
        __stcs(&out4[(size_t)d * (L_ / 4) + q],
               make_float4(pv.x * ud, pv.y * ud, pv.z * ud, pv.w * ud));
    }
}

extern "C" void kernel_launch(void* const* d_in, const int* in_sizes, int n_in,
                              void* d_out, int out_size) {
    const float* h_v   = (const float*)d_in[0];  // [B, C, L]
    const float* wq    = (const float*)d_in[1];  // [64]
    const float* wk    = (const float*)d_in[2];  // [64]
    const float* wv    = (const float*)d_in[3];  // [64]
    const float* w_out = (const float*)d_in[4];  // [512, 64]
    float* out = (float*)d_out;                  // [B, 512, L]

    prep_kernel<<<D_ / 16, 256>>>(wq, wk, wv, w_out);
    pool_outer_kernel<<<B_ * (L_ / 32), 256>>>(h_v, out);
}

// round 3
// speedup vs baseline: 1.2532x; 1.1921x over previous
#include <cuda_runtime.h>
#include <cuda_bf16.h>
#include <cstddef>

// Problem constants (fixed shapes per reference)
constexpr int B_ = 16;
constexpr int C_ = 256;
constexpr int L_ = 8192;
constexpr int D_ = 512;   // d_inner
constexpr int A_ = 64;    // att_dim

// Scratch: u[d] = sum_a w_out[d,a]*wv[a]; coef = <wq,wk>/sqrt(att_dim)
__device__ float g_u[D_];
__device__ float g_coef;

// 32 blocks x 256 threads. Block g computes u[d] for d in [g*16, g*16+16).
__global__ void prep_kernel(const float* __restrict__ wq,
                            const float* __restrict__ wk,
                            const float* __restrict__ wv,
                            const float* __restrict__ w_out) {
    const int t = threadIdx.x;
    const int g = blockIdx.x;
    const int dl   = t >> 4;
    const int part = t & 15;
    const int d = g * 16 + dl;

    const float4* w4  = reinterpret_cast<const float4*>(w_out + (size_t)d * A_);
    const float4  wv4 = reinterpret_cast<const float4*>(wv)[part];
    const float4  a4  = w4[part];
    float acc = a4.x * wv4.x + a4.y * wv4.y + a4.z * wv4.z + a4.w * wv4.w;
#pragma unroll
    for (int m = 1; m < 16; m <<= 1)
        acc += __shfl_xor_sync(0xffffffffu, acc, m);
    if (part == 0) g_u[d] = acc;

    // coef: block 0, warp 0
    if (g == 0 && t < 32) {
        float p = wq[t] * wk[t] + wq[t + 32] * wk[t + 32];
#pragma unroll
        for (int m = 16; m >= 1; m >>= 1)
            p += __shfl_xor_sync(0xffffffffu, p, m);
        if (t == 0) g_coef = p * 0.125f;  // 1/sqrt(64)
    }
}

// One block = (one b, 32 consecutive l). 256 threads = 8 c-groups x 32 l.
// Each thread keeps its 32 h values in registers -> h_v read exactly once.
// (R1 structure: scalar LDG.32 = one 128B line per warp per instruction,
// MLP_p1 = 32; smem reductions, no shuffles, 48 regs.)
__global__ void __launch_bounds__(256)
pool_outer_kernel(const float* __restrict__ h_v, float* __restrict__ out) {
    __shared__ float s_u[D_];
    __shared__ float s_red[256];
    __shared__ float s_red2[256];
    __shared__ float s_sval[32];
    __shared__ __align__(16) float s_pooled[32];

    const int tid = threadIdx.x;
    const int ll  = tid & 31;   // l within tile
    const int cg  = tid >> 5;   // c-group 0..7

    const int bidx   = blockIdx.x;          // 16 * 256 = 4096 blocks
    const int b      = bidx >> 8;
    const int l_base = (bidx & 255) << 5;

    // hoist coef before any barrier
    const float coef = g_coef;

    // stage u into smem (2 per thread)
    s_u[tid]       = g_u[tid];
    s_u[tid + 256] = g_u[tid + 256];

    // ---- single read of h_v: 32 values per thread, coalesced per warp ----
    const float* p = h_v + ((size_t)b * C_ + (size_t)cg * 32) * L_ + l_base + ll;
    float h[32];
#pragma unroll
    for (int i = 0; i < 32; i++) h[i] = __ldcs(p + (size_t)i * L_);

    // ---- mean over C ----
    float sum = 0.f;
#pragma unroll
    for (int i = 0; i < 32; i++) sum += h[i];
    s_red[tid] = sum;
    __syncthreads();
    if (tid < 32) {
        float t = 0.f;
#pragma unroll
        for (int j = 0; j < 8; j++) t += s_red[tid + 32 * j];
        s_sval[tid] = t * ((1.0f / 256.0f) * coef);  // fold mean scale + qk/sqrt(A)
    }
    __syncthreads();

    const float coef2 = s_sval[ll];  // per-l logit scale

    // ---- softmax-weighted sum (max-free: |logit| bounded ~1.2) ----
    float se = 0.f, seh = 0.f;
#pragma unroll
    for (int i = 0; i < 32; i++) {
        float e = __expf(h[i] * coef2);
        se  += e;
        seh += e * h[i];
    }
    s_red[tid]  = se;
    s_red2[tid] = seh;
    __syncthreads();
    if (tid < 32) {
        float te = 0.f, teh = 0.f;
#pragma unroll
        for (int j = 0; j < 8; j++) {
            te  += s_red[tid + 32 * j];
            teh += s_red2[tid + 32 * j];
        }
        s_pooled[tid] = teh / te;
    }
    __syncthreads();

    // ---- epilogue: out[b,d,l] = pooled[b,l] * u[d], float4 streaming stores ----
    const float4* pool4 = reinterpret_cast<const float4*>(s_pooled);  // 8 float4
    float4* out4 = reinterpret_cast<float4*>(out + (size_t)b * D_ * L_ + l_base);
    // 512 d-rows x 8 float4 = 4096 vec stores per block; 16 per thread
#pragma unroll
    for (int k = 0; k < 16; k++) {
        int idx = k * 256 + tid;
        int d   = idx >> 3;
        int lq  = idx & 7;
        float ud = s_u[d];
        float4 pv = pool4[lq];
        __stcs(&out4[(size_t)d * (L_ / 4) + lq],
               make_float4(pv.x * ud, pv.y * ud, pv.z * ud, pv.w * ud));
    }
}

extern "C" void kernel_launch(void* const* d_in, const int* in_sizes, int n_in,
                              void* d_out, int out_size) {
    const float* h_v   = (const float*)d_in[0];  // [B, C, L]
    const float* wq    = (const float*)d_in[1];  // [64]
    const float* wk    = (const float*)d_in[2];  // [64]
    const float* wv    = (const float*)d_in[3];  // [64]
    const float* w_out = (const float*)d_in[4];  // [512, 64]
    float* out = (float*)d_out;                  // [B, 512, L]

    prep_kernel<<<D_ / 16, 256>>>(wq, wk, wv, w_out);
    pool_outer_kernel<<<B_ * (L_ / 32), 256>>>(h_v, out);
}